// round 15
// baseline (speedup 1.0000x reference)
#include <cuda_runtime.h>
#include <cstdint>

// Problem constants
#define NB   8
#define NS   1024
#define ND   1024
#define NH   16
#define MROWS (NB * NS)   // 8192

// ---------------------------------------------------------------------------
// Device scratch (allocation-free rule: __device__ globals)
// ---------------------------------------------------------------------------
__device__ float g_q[(size_t)MROWS * ND];    // tf32-rounded (GEMM epilogue)
__device__ float g_k[(size_t)MROWS * ND];    // tf32-rounded
__device__ float g_v[(size_t)MROWS * ND];    // tf32-rounded
__device__ float g_o[(size_t)MROWS * ND];    // tf32-rounded (attn epilogue)
__device__ float g_x[(size_t)MROWS * ND];    // fp32 (residual sum, LN input)
__device__ float g_yr[(size_t)MROWS * ND];   // tf32-rounded y
__device__ float g_wr[(size_t)4 * ND * ND];  // tf32-rounded Wq,Wk,Wv,Wm
__device__ float g_bias[MROWS];              // additive mask bias per (b, key)

// ---------------------------------------------------------------------------
// Helpers
// ---------------------------------------------------------------------------
__device__ __forceinline__ unsigned f2tf(float x) {
    unsigned u;
    asm("cvt.rna.tf32.f32 %0, %1;" : "=r"(u) : "f"(x));
    return u;
}
__device__ __forceinline__ float rtf(float x) { return __uint_as_float(f2tf(x)); }

__device__ __forceinline__ void mma_tf32(float* d, const unsigned* a, const unsigned* b) {
    asm volatile(
        "mma.sync.aligned.m16n8k8.row.col.f32.tf32.tf32.f32 "
        "{%0,%1,%2,%3}, {%4,%5,%6,%7}, {%8,%9}, {%0,%1,%2,%3};\n"
        : "+f"(d[0]), "+f"(d[1]), "+f"(d[2]), "+f"(d[3])
        : "r"(a[0]), "r"(a[1]), "r"(a[2]), "r"(a[3]), "r"(b[0]), "r"(b[1]));
}

__device__ __forceinline__ void cp16(unsigned smem_addr, const float* gmem) {
    asm volatile("cp.async.cg.shared.global [%0], [%1], 16;\n"
                 :: "r"(smem_addr), "l"(gmem));
}
__device__ __forceinline__ void cp_commit() {
    asm volatile("cp.async.commit_group;\n");
}
template <int N>
__device__ __forceinline__ void cp_wait() {
    asm volatile("cp.async.wait_group %0;\n" :: "n"(N));
}

// ---------------------------------------------------------------------------
// Mask conversion: robust to int32 / float32 / byte-bool encodings.
// ---------------------------------------------------------------------------
__global__ void mask_convert(const void* __restrict__ mask) {
    __shared__ int flag_not01;
    __shared__ int flag_notfp;
    if (threadIdx.x == 0) { flag_not01 = 0; flag_notfp = 0; }
    __syncthreads();
    const unsigned* w = (const unsigned*)mask;
    for (int i = threadIdx.x; i < 2048; i += blockDim.x) {
        unsigned v = w[i];
        if (v > 1u) flag_not01 = 1;
        if (v != 0u && v != 0x3F800000u) flag_notfp = 1;
    }
    __syncthreads();
    const int mode = (flag_not01 == 0) ? 0 : ((flag_notfp == 0) ? 1 : 2);
    for (int i = threadIdx.x; i < MROWS; i += blockDim.x) {
        bool on;
        if (mode == 0)      on = ((const int*)mask)[i] != 0;
        else if (mode == 1) on = ((const float*)mask)[i] != 0.0f;
        else                on = ((const unsigned char*)mask)[i] != 0;
        g_bias[i] = on ? -1e9f : 0.0f;
    }
}

// ---------------------------------------------------------------------------
// Pre-round y and all four W to tf32 (rna): hot loops load raw bits, no cvt.
// ---------------------------------------------------------------------------
__global__ __launch_bounds__(256) void round_tf32(
    const float* __restrict__ y,
    const float* __restrict__ Wq, const float* __restrict__ Wk,
    const float* __restrict__ Wv, const float* __restrict__ Wm)
{
    const int NY = MROWS * ND / 4;
    const int NW = ND * ND / 4;
    const int i = blockIdx.x * 256 + threadIdx.x;
    const float4* src;
    float4* dst;
    if (i < NY) {
        src = (const float4*)y + i;
        dst = (float4*)g_yr + i;
    } else {
        const int j = i - NY;
        const int w = j / NW, o = j - w * NW;
        const float* s = (w == 0) ? Wq : (w == 1) ? Wk : (w == 2) ? Wv : Wm;
        src = (const float4*)s + o;
        dst = (float4*)(g_wr + (size_t)w * ND * ND) + o;
    }
    const float4 v = *src;
    *dst = make_float4(rtf(v.x), rtf(v.y), rtf(v.z), rtf(v.w));
}

// ---------------------------------------------------------------------------
// tf32 GEMM (NT), occupancy-tuned with STATIC smem: CTA 128(m)x64(n),
// k-chunk 16, 2 cp.async stages (30720B static). 8 warps as 4(m)x2(n),
// warp tile 32x32 (acc = 32 regs -> 3 CTAs/SM via __launch_bounds__(256,3)).
// ASTR=20 => fragment LDS banks (4g + t + const) bijective => conflict-free.
// ---------------------------------------------------------------------------
#define KCH   16
#define ASTR  20
#define NITER (ND / KCH)   // 64

template <bool RES, bool ROUND>
__device__ __forceinline__ void gemm_body(
    const float* __restrict__ A, const float* __restrict__ W,
    const float* __restrict__ bias, const float* __restrict__ res_y,
    float* __restrict__ C)
{
    __shared__ float As[2][128 * ASTR];   // 20480 B
    __shared__ float Bs[2][64 * ASTR];    // 10240 B

    const int tid  = threadIdx.x;
    const int warp = tid >> 5, lane = tid & 31;
    const int g = lane >> 2, t = lane & 3;
    const int wm = warp >> 1, wn = warp & 1;      // 4(m) x 2(n)
    const int row0 = blockIdx.y * 128;
    const int col0 = blockIdx.x * 64;

    // Loaders. A: 128 rows x 16 floats -> 8 floats/thread (2 cp16).
    //          B:  64 rows x 16 floats -> 4 floats/thread (1 cp16).
    const int arow = tid >> 1, acol = (tid & 1) << 3;
    const int brow = tid >> 2, bcol = (tid & 3) << 2;
    const float* ag = A + (size_t)(row0 + arow) * ND + acol;
    const float* bg = W + (size_t)(col0 + brow) * ND + bcol;

    const unsigned saA[2] = {
        (unsigned)__cvta_generic_to_shared(&As[0][arow * ASTR + acol]),
        (unsigned)__cvta_generic_to_shared(&As[1][arow * ASTR + acol]) };
    const unsigned saB[2] = {
        (unsigned)__cvta_generic_to_shared(&Bs[0][brow * ASTR + bcol]),
        (unsigned)__cvta_generic_to_shared(&Bs[1][brow * ASTR + bcol]) };

    auto load_stage = [&](int st, int kc) {
        const float* a = ag + kc * KCH;
        const float* b = bg + kc * KCH;
        cp16(saA[st],       a);
        cp16(saA[st] + 16u, a + 4);
        cp16(saB[st],       b);
    };

    load_stage(0, 0); cp_commit();
    load_stage(1, 1); cp_commit();

    float acc[2][4][4];
#pragma unroll
    for (int mt = 0; mt < 2; ++mt)
#pragma unroll
        for (int nt = 0; nt < 4; ++nt)
#pragma unroll
            for (int j = 0; j < 4; ++j) acc[mt][nt][j] = 0.0f;

    const int afoff = (wm * 32 + g) * ASTR;
    const int bfoff = (wn * 32 + g) * ASTR;

#pragma unroll 1
    for (int kc = 0; kc < NITER; ++kc) {
        const int cur = kc & 1;
        const float* Ab = As[cur];
        const float* Bb = Bs[cur];
        cp_wait<1>();        // chunk kc's copies complete
        __syncthreads();     // ...and visible to all

#pragma unroll
        for (int ks = 0; ks < 2; ++ks) {
            unsigned af[2][4], bf[4][2];
            const int kb = ks * 8 + t;
#pragma unroll
            for (int mt = 0; mt < 2; ++mt) {
                const float* p = Ab + afoff + mt * 16 * ASTR + kb;
                af[mt][0] = __float_as_uint(p[0]);
                af[mt][1] = __float_as_uint(p[8 * ASTR]);
                af[mt][2] = __float_as_uint(p[4]);
                af[mt][3] = __float_as_uint(p[8 * ASTR + 4]);
            }
#pragma unroll
            for (int nt = 0; nt < 4; ++nt) {
                const float* p = Bb + bfoff + nt * 8 * ASTR + kb;
                bf[nt][0] = __float_as_uint(p[0]);
                bf[nt][1] = __float_as_uint(p[4]);
            }
#pragma unroll
            for (int mt = 0; mt < 2; ++mt)
#pragma unroll
                for (int nt = 0; nt < 4; ++nt)
                    mma_tf32(acc[mt][nt], af[mt], bf[nt]);
        }
        __syncthreads();     // stage cur readers done before refill

        const int kn = (kc + 2 < NITER) ? kc + 2 : 0;   // tail dummy
        load_stage(cur, kn);
        cp_commit();
    }

    // Epilogue: bias (+residual), optional tf32 rounding, float2 stores
#pragma unroll
    for (int nt = 0; nt < 4; ++nt) {
        const int c = col0 + wn * 32 + nt * 8 + 2 * t;
        const float2 bb = *(const float2*)&bias[c];
#pragma unroll
        for (int mt = 0; mt < 2; ++mt) {
            const int r = row0 + wm * 32 + mt * 16 + g;
            float2 o0 = make_float2(acc[mt][nt][0] + bb.x, acc[mt][nt][1] + bb.y);
            float2 o1 = make_float2(acc[mt][nt][2] + bb.x, acc[mt][nt][3] + bb.y);
            if (RES) {
                const float2 r0v = *(const float2*)&res_y[(size_t)r * ND + c];
                const float2 r1v = *(const float2*)&res_y[(size_t)(r + 8) * ND + c];
                o0.x += r0v.x; o0.y += r0v.y;
                o1.x += r1v.x; o1.y += r1v.y;
            }
            if (ROUND) {
                o0.x = rtf(o0.x); o0.y = rtf(o0.y);
                o1.x = rtf(o1.x); o1.y = rtf(o1.y);
            }
            *(float2*)&C[(size_t)r * ND + c]       = o0;
            *(float2*)&C[(size_t)(r + 8) * ND + c] = o1;
        }
    }
}

__global__ __launch_bounds__(256, 3) void qkv_gemm(
    const float* __restrict__ bq, const float* __restrict__ bk,
    const float* __restrict__ bv)
{
    const float* W = g_wr + (size_t)blockIdx.z * ND * ND;
    const float* bias = (blockIdx.z == 0) ? bq : (blockIdx.z == 1) ? bk : bv;
    float* C = (blockIdx.z == 0) ? g_q : (blockIdx.z == 1) ? g_k : g_v;
    gemm_body<false, true>(g_yr, W, bias, nullptr, C);
}

__global__ __launch_bounds__(256, 3) void proj_gemm(
    const float* __restrict__ bm, const float* __restrict__ res_y)
{
    gemm_body<true, false>(g_o, g_wr + (size_t)3 * ND * ND, bm, res_y, g_x);
}

// ---------------------------------------------------------------------------
// Flash attention, tf32 mma (R9-proven, static smem 36352B). Inputs
// pre-rounded tf32 -> loader is raw copies. CTA = 128 q-rows x 1 head,
// 8 warps x 16-row bands, Q fragments in registers, BN=32 chunks.
// Epilogue rounds O to tf32 (input for proj_gemm).
// ---------------------------------------------------------------------------
__global__ __launch_bounds__(256, 2) void attn_mma()
{
    __shared__ unsigned Ks[32 * 68];
    __shared__ unsigned Vs[32 * 72];
    __shared__ unsigned Ps[128 * 36];

    const int tid  = threadIdx.x;
    const int warp = tid >> 5, lane = tid & 31;
    const int g = lane >> 2, t = lane & 3;
    const int b  = blockIdx.y >> 4;
    const int h  = blockIdx.y & 15;
    const int q0 = blockIdx.x << 7;

    // Q fragments (pre-scaled by 1/8; exact on tf32 values)
    unsigned qf[8][4];
    {
        const int r0 = b * NS + q0 + warp * 16 + g;
        const float* qp  = g_q + ((size_t)r0 << 10) + (h << 6);
        const float* qp8 = qp + ((size_t)8 << 10);
#pragma unroll
        for (int ks = 0; ks < 8; ++ks) {
            const int c = ks * 8 + t;
            qf[ks][0] = __float_as_uint(qp[c] * 0.125f);
            qf[ks][1] = __float_as_uint(qp8[c] * 0.125f);
            qf[ks][2] = __float_as_uint(qp[c + 4] * 0.125f);
            qf[ks][3] = __float_as_uint(qp8[c + 4] * 0.125f);
        }
    }

    float of[8][4];
#pragma unroll
    for (int nt = 0; nt < 8; ++nt)
#pragma unroll
        for (int j = 0; j < 4; ++j) of[nt][j] = 0.0f;
    float m0 = -1e30f, m1 = -1e30f, l0 = 0.0f, l1 = 0.0f;

    const size_t kvbase = ((size_t)b << 20) + (size_t)(h << 6);
    const int key = tid >> 3;
    const int cb  = (tid & 7) << 3;

#pragma unroll 1
    for (int kc = 0; kc < 32; ++kc) {
        const int key0 = kc << 5;
        __syncthreads();
        {
            const float* kp = g_k + kvbase + ((size_t)(key0 + key) << 10) + cb;
            const float* vp = g_v + kvbase + ((size_t)(key0 + key) << 10) + cb;
            unsigned* kd = &Ks[key * 68 + cb];
            unsigned* vd = &Vs[key * 72 + cb];
            *(uint4*)kd       = *(const uint4*)kp;
            *(uint4*)(kd + 4) = *(const uint4*)(kp + 4);
            *(uint4*)vd       = *(const uint4*)vp;
            *(uint4*)(vd + 4) = *(const uint4*)(vp + 4);
        }
        __syncthreads();

        // S = Q @ K^T : warp band 16 x 32
        float sf[4][4];
#pragma unroll
        for (int nt = 0; nt < 4; ++nt)
#pragma unroll
            for (int j = 0; j < 4; ++j) sf[nt][j] = 0.0f;
#pragma unroll
        for (int ks = 0; ks < 8; ++ks) {
#pragma unroll
            for (int nt = 0; nt < 4; ++nt) {
                unsigned bf[2];
                const unsigned* p = &Ks[(nt * 8 + g) * 68 + ks * 8 + t];
                bf[0] = p[0];
                bf[1] = p[4];
                mma_tf32(sf[nt], qf[ks], bf);
            }
        }

        // mask bias
#pragma unroll
        for (int nt = 0; nt < 4; ++nt) {
            const float2 bb = *(const float2*)&g_bias[(b << 10) + key0 + nt * 8 + 2 * t];
            sf[nt][0] += bb.x; sf[nt][1] += bb.y;
            sf[nt][2] += bb.x; sf[nt][3] += bb.y;
        }

        // online softmax stats (lanes 4g+t: xor 1,2 stay in-row)
        float mx0 = -1e30f, mx1 = -1e30f;
#pragma unroll
        for (int nt = 0; nt < 4; ++nt) {
            mx0 = fmaxf(mx0, fmaxf(sf[nt][0], sf[nt][1]));
            mx1 = fmaxf(mx1, fmaxf(sf[nt][2], sf[nt][3]));
        }
        mx0 = fmaxf(mx0, __shfl_xor_sync(0xffffffffu, mx0, 1));
        mx0 = fmaxf(mx0, __shfl_xor_sync(0xffffffffu, mx0, 2));
        mx1 = fmaxf(mx1, __shfl_xor_sync(0xffffffffu, mx1, 1));
        mx1 = fmaxf(mx1, __shfl_xor_sync(0xffffffffu, mx1, 2));

        const float nm0 = fmaxf(m0, mx0);
        const float nm1 = fmaxf(m1, mx1);
        const float al0 = __expf(m0 - nm0);
        const float al1 = __expf(m1 - nm1);

        float sum0 = 0.0f, sum1 = 0.0f;
#pragma unroll
        for (int nt = 0; nt < 4; ++nt) {
            sf[nt][0] = __expf(sf[nt][0] - nm0);
            sf[nt][1] = __expf(sf[nt][1] - nm0);
            sf[nt][2] = __expf(sf[nt][2] - nm1);
            sf[nt][3] = __expf(sf[nt][3] - nm1);
            sum0 += sf[nt][0] + sf[nt][1];
            sum1 += sf[nt][2] + sf[nt][3];
        }
        sum0 += __shfl_xor_sync(0xffffffffu, sum0, 1);
        sum0 += __shfl_xor_sync(0xffffffffu, sum0, 2);
        sum1 += __shfl_xor_sync(0xffffffffu, sum1, 1);
        sum1 += __shfl_xor_sync(0xffffffffu, sum1, 2);
        l0 = l0 * al0 + sum0;  m0 = nm0;
        l1 = l1 * al1 + sum1;  m1 = nm1;

        // P fragments (tf32-rounded) -> own-warp smem rows
        {
            const int pr = warp * 16 + g;
#pragma unroll
            for (int nt = 0; nt < 4; ++nt) {
                const int c = nt * 8 + 2 * t;
                Ps[pr * 36 + c]           = f2tf(sf[nt][0]);
                Ps[pr * 36 + c + 1]       = f2tf(sf[nt][1]);
                Ps[(pr + 8) * 36 + c]     = f2tf(sf[nt][2]);
                Ps[(pr + 8) * 36 + c + 1] = f2tf(sf[nt][3]);
            }
        }
        __syncwarp();

        // O = O*alpha + P @ V
#pragma unroll
        for (int nt = 0; nt < 8; ++nt) {
            of[nt][0] *= al0; of[nt][1] *= al0;
            of[nt][2] *= al1; of[nt][3] *= al1;
        }
#pragma unroll
        for (int kt = 0; kt < 4; ++kt) {
            unsigned af[4];
            const unsigned* p = &Ps[(warp * 16 + g) * 36 + kt * 8 + t];
            af[0] = p[0];
            af[1] = p[8 * 36];
            af[2] = p[4];
            af[3] = p[8 * 36 + 4];
#pragma unroll
            for (int nt = 0; nt < 8; ++nt) {
                unsigned bf[2];
                bf[0] = Vs[(kt * 8 + t) * 72 + nt * 8 + g];
                bf[1] = Vs[(kt * 8 + t + 4) * 72 + nt * 8 + g];
                mma_tf32(of[nt], af, bf);
            }
        }
    }

    // finalize: divide by l, round to tf32 (proj input), store
    const float r0i = 1.0f / l0;
    const float r1i = 1.0f / l1;
    float* op  = g_o + ((size_t)(b * NS + q0 + warp * 16 + g) << 10) + (h << 6);
    float* op8 = op + ((size_t)8 << 10);
#pragma unroll
    for (int nt = 0; nt < 8; ++nt) {
        const int c = nt * 8 + 2 * t;
        *(float2*)&op[c]  = make_float2(rtf(of[nt][0] * r0i), rtf(of[nt][1] * r0i));
        *(float2*)&op8[c] = make_float2(rtf(of[nt][2] * r1i), rtf(of[nt][3] * r1i));
    }
}

// ---------------------------------------------------------------------------
// LayerNorm (torch semantics): unbiased std (ddof=1), eps added to std.
// ---------------------------------------------------------------------------
__global__ __launch_bounds__(256) void ln_kernel(
    const float* __restrict__ a2, const float* __restrict__ b2,
    float* __restrict__ out)
{
    const int row = blockIdx.x;
    const int tid = threadIdx.x;
    const float* xr = g_x + (size_t)row * ND;
    const float4 v = *(const float4*)(xr + 4 * tid);

    float s  = v.x + v.y + v.z + v.w;
    float sq = v.x * v.x + v.y * v.y + v.z * v.z + v.w * v.w;
#pragma unroll
    for (int o = 16; o > 0; o >>= 1) {
        s  += __shfl_xor_sync(0xffffffffu, s, o);
        sq += __shfl_xor_sync(0xffffffffu, sq, o);
    }
    __shared__ float sh_s[8], sh_q[8];
    const int w = tid >> 5, ln = tid & 31;
    if (ln == 0) { sh_s[w] = s; sh_q[w] = sq; }
    __syncthreads();
    if (w == 0) {
        s  = (ln < 8) ? sh_s[ln] : 0.0f;
        sq = (ln < 8) ? sh_q[ln] : 0.0f;
#pragma unroll
        for (int o = 4; o > 0; o >>= 1) {
            s  += __shfl_xor_sync(0xffffffffu, s, o);
            sq += __shfl_xor_sync(0xffffffffu, sq, o);
        }
        if (ln == 0) { sh_s[0] = s; sh_q[0] = sq; }
    }
    __syncthreads();
    s  = sh_s[0];
    sq = sh_q[0];

    const float mean = s * (1.0f / 1024.0f);
    const float var  = (sq - s * mean) * (1.0f / 1023.0f);
    const float inv  = 1.0f / (sqrtf(fmaxf(var, 0.0f)) + 1e-6f);

    const float4 av = *(const float4*)(a2 + 4 * tid);
    const float4 bv = *(const float4*)(b2 + 4 * tid);
    float4 o;
    o.x = av.x * (v.x - mean) * inv + bv.x;
    o.y = av.y * (v.y - mean) * inv + bv.y;
    o.z = av.z * (v.z - mean) * inv + bv.z;
    o.w = av.w * (v.w - mean) * inv + bv.w;
    *(float4*)(out + (size_t)row * ND + 4 * tid) = o;
}

// ---------------------------------------------------------------------------
// Launch (no attribute calls, no dynamic smem — all static <= 48KB)
// ---------------------------------------------------------------------------
extern "C" void kernel_launch(void* const* d_in, const int* in_sizes, int n_in,
                              void* d_out, int out_size)
{
    const float* y  = (const float*)d_in[0];
    const void*  mk = d_in[1];
    const float* Wq = (const float*)d_in[2];
    const float* bq = (const float*)d_in[3];
    const float* Wk = (const float*)d_in[4];
    const float* bk = (const float*)d_in[5];
    const float* Wv = (const float*)d_in[6];
    const float* bv = (const float*)d_in[7];
    const float* Wm = (const float*)d_in[8];
    const float* bm = (const float*)d_in[9];
    const float* a2 = (const float*)d_in[10];
    const float* b2 = (const float*)d_in[11];
    float* out = (float*)d_out;

    mask_convert<<<1, 256>>>(mk);
    round_tf32<<<(MROWS * ND / 4 + 4 * ND * ND / 4) / 256, 256>>>(y, Wq, Wk, Wv, Wm);

    qkv_gemm<<<dim3(ND / 64, MROWS / 128, 3), 256>>>(bq, bk, bv);

    attn_mma<<<dim3(NS / 128, NB * NH), 256>>>();   // (8, 128)

    proj_gemm<<<dim3(ND / 64, MROWS / 128), 256>>>(bm, y);

    ln_kernel<<<MROWS, 256>>>(a2, b2, out);
}

// round 17
// speedup vs baseline: 1.3651x; 1.3651x over previous
#include <cuda_runtime.h>
#include <cstdint>

// Problem constants
#define NB   8
#define NS   1024
#define ND   1024
#define NH   16
#define MROWS (NB * NS)   // 8192

// ---------------------------------------------------------------------------
// Device scratch (allocation-free rule: __device__ globals)
// ---------------------------------------------------------------------------
__device__ float g_q[(size_t)MROWS * ND];    // tf32-rounded, normal layout
__device__ float g_k[(size_t)MROWS * ND];    // tf32-rounded, normal layout
__device__ float g_v[(size_t)MROWS * ND];    // tf32-rounded, normal layout
__device__ float g_o[(size_t)MROWS * ND];    // tf32-rounded, A-PERMUTED (proj input)
__device__ float g_x[(size_t)MROWS * ND];    // fp32 normal (residual sum, LN input)
__device__ float g_yr[(size_t)MROWS * ND];   // tf32-rounded y, A-PERMUTED
__device__ float g_wr[(size_t)4 * ND * ND];  // tf32-rounded W, B-PERMUTED
__device__ float g_bias[MROWS];              // additive mask bias per (b, key)

// ---------------------------------------------------------------------------
// MMA-native permuted layouts (word indices; ncols = 1024).
// A (m16k8 frags): 16x16 blocks of 256 words:
//   [m-block][k-chunk] -> ks(128) -> lane(4g+t)*4 -> j = j0 + 2*j1
//   j0 = row+8 select, j1 = col+4 select  (matches HMMA a0..a3 order)
// B (n8k8 frags): 8x16 blocks of 128 words:
//   [n-block][k-chunk] -> ks(64) -> lane*2 -> j1 = col+4 select
// ---------------------------------------------------------------------------
__device__ __forceinline__ size_t permA(int row, int col) {
    return ((size_t)((row >> 4) * 64 + (col >> 4)) << 8)
         + (size_t)((((col >> 3) & 1) << 7)
         + (((row & 7) * 4 + (col & 3)) << 2)
         + ((row >> 3) & 1) + (((col >> 2) & 1) << 1));
}
__device__ __forceinline__ size_t permB(int row, int col) {
    return ((size_t)((row >> 3) * 64 + (col >> 4)) << 7)
         + (size_t)((((col >> 3) & 1) << 6)
         + (((row & 7) * 4 + (col & 3)) << 1)
         + ((col >> 2) & 1));
}

// ---------------------------------------------------------------------------
// Helpers
// ---------------------------------------------------------------------------
__device__ __forceinline__ unsigned f2tf(float x) {
    unsigned u;
    asm("cvt.rna.tf32.f32 %0, %1;" : "=r"(u) : "f"(x));
    return u;
}
__device__ __forceinline__ float rtf(float x) { return __uint_as_float(f2tf(x)); }

__device__ __forceinline__ void mma_tf32(float* d, const unsigned* a, const unsigned* b) {
    asm volatile(
        "mma.sync.aligned.m16n8k8.row.col.f32.tf32.tf32.f32 "
        "{%0,%1,%2,%3}, {%4,%5,%6,%7}, {%8,%9}, {%0,%1,%2,%3};\n"
        : "+f"(d[0]), "+f"(d[1]), "+f"(d[2]), "+f"(d[3])
        : "r"(a[0]), "r"(a[1]), "r"(a[2]), "r"(a[3]), "r"(b[0]), "r"(b[1]));
}

__device__ __forceinline__ void cp16(unsigned smem_addr, const float* gmem) {
    asm volatile("cp.async.cg.shared.global [%0], [%1], 16;\n"
                 :: "r"(smem_addr), "l"(gmem));
}
__device__ __forceinline__ void cp_commit() {
    asm volatile("cp.async.commit_group;\n");
}
template <int N>
__device__ __forceinline__ void cp_wait() {
    asm volatile("cp.async.wait_group %0;\n" :: "n"(N));
}

// ---------------------------------------------------------------------------
// Mask conversion: robust to int32 / float32 / byte-bool encodings.
// ---------------------------------------------------------------------------
__global__ void mask_convert(const void* __restrict__ mask) {
    __shared__ int flag_not01;
    __shared__ int flag_notfp;
    if (threadIdx.x == 0) { flag_not01 = 0; flag_notfp = 0; }
    __syncthreads();
    const unsigned* w = (const unsigned*)mask;
    for (int i = threadIdx.x; i < 2048; i += blockDim.x) {
        unsigned v = w[i];
        if (v > 1u) flag_not01 = 1;
        if (v != 0u && v != 0x3F800000u) flag_notfp = 1;
    }
    __syncthreads();
    const int mode = (flag_not01 == 0) ? 0 : ((flag_notfp == 0) ? 1 : 2);
    for (int i = threadIdx.x; i < MROWS; i += blockDim.x) {
        bool on;
        if (mode == 0)      on = ((const int*)mask)[i] != 0;
        else if (mode == 1) on = ((const float*)mask)[i] != 0.0f;
        else                on = ((const unsigned char*)mask)[i] != 0;
        g_bias[i] = on ? -1e9f : 0.0f;
    }
}

// ---------------------------------------------------------------------------
// Pre-round y (-> A-perm) and all four W (-> B-perm) to tf32 (rna).
// ---------------------------------------------------------------------------
__global__ __launch_bounds__(256) void round_tf32(
    const float* __restrict__ y,
    const float* __restrict__ Wq, const float* __restrict__ Wk,
    const float* __restrict__ Wv, const float* __restrict__ Wm)
{
    const int NY = MROWS * ND / 4;
    const int NW = ND * ND / 4;
    const int i = blockIdx.x * 256 + threadIdx.x;
    if (i < NY) {
        const float4 v = ((const float4*)y)[i];
        const int row = i >> 8;
        const int c0  = (i & 255) << 2;
        g_yr[permA(row, c0 + 0)] = rtf(v.x);
        g_yr[permA(row, c0 + 1)] = rtf(v.y);
        g_yr[permA(row, c0 + 2)] = rtf(v.z);
        g_yr[permA(row, c0 + 3)] = rtf(v.w);
    } else {
        const int j = i - NY;
        const int w = j / NW, o = j - w * NW;
        const float* s = (w == 0) ? Wq : (w == 1) ? Wk : (w == 2) ? Wv : Wm;
        const float4 v = ((const float4*)s)[o];
        float* d = g_wr + (size_t)w * ND * ND;
        const int row = o >> 8;
        const int c0  = (o & 255) << 2;
        d[permB(row, c0 + 0)] = rtf(v.x);
        d[permB(row, c0 + 1)] = rtf(v.y);
        d[permB(row, c0 + 2)] = rtf(v.z);
        d[permB(row, c0 + 3)] = rtf(v.w);
    }
}

// ---------------------------------------------------------------------------
// tf32 GEMM (NT) on permuted operands: C = A @ W^T + bias (+ res)
// CTA 128x128, k-chunk 16, 2 cp.async stages (32KB static). 8 warps as
// 2(m)x4(n), warp tile 64x32. Fragment loads are LDS.128 (A) / LDS.64 (B) —
// lane-consecutive => conflict-free, no padding/swizzle.
// Per k8-step issue slots: 4 LDS.128 + 4 LDS.64 + 16 HMMA (was 24 LDS + 16).
// ---------------------------------------------------------------------------
#define KCH   16
#define NITER (ND / KCH)   // 64

template <bool RES, bool ROUND>
__device__ __forceinline__ void gemm_body(
    const float* __restrict__ Ap, const float* __restrict__ Bp,
    const float* __restrict__ bias, const float* __restrict__ res_y,
    float* __restrict__ C)
{
    __shared__ float As[2][2048];   // 8 m-blocks x 256 words
    __shared__ float Bs[2][2048];   // 16 n-blocks x 128 words

    const int tid  = threadIdx.x;
    const int warp = tid >> 5, lane = tid & 31;
    const int g = lane >> 2, t = lane & 3;
    const int wm = warp & 1, wn = warp >> 1;      // 2(m) x 4(n)
    const int row0 = blockIdx.y * 128;
    const int col0 = blockIdx.x * 128;

    // Loaders: 8 words/thread for A and for B (linear in permuted global)
    const float* agbase = Ap + ((size_t)((row0 >> 4) + (tid >> 5)) << 6 << 8)
                             + ((tid << 3) & 255);
    const float* bgbase = Bp + ((size_t)((col0 >> 3) + (tid >> 4)) << 6 << 7)
                             + ((tid << 3) & 127);

    const unsigned saA[2] = {
        (unsigned)__cvta_generic_to_shared(&As[0][tid << 3]),
        (unsigned)__cvta_generic_to_shared(&As[1][tid << 3]) };
    const unsigned saB[2] = {
        (unsigned)__cvta_generic_to_shared(&Bs[0][tid << 3]),
        (unsigned)__cvta_generic_to_shared(&Bs[1][tid << 3]) };

    auto load_stage = [&](int st, int kc) {
        const float* a = agbase + (kc << 8);
        const float* b = bgbase + (kc << 7);
        cp16(saA[st],       a);
        cp16(saA[st] + 16u, a + 4);
        cp16(saB[st],       b);
        cp16(saB[st] + 16u, b + 4);
    };

    load_stage(0, 0); cp_commit();
    load_stage(1, 1); cp_commit();

    float acc[4][4][4];
#pragma unroll
    for (int mt = 0; mt < 4; ++mt)
#pragma unroll
        for (int nt = 0; nt < 4; ++nt)
#pragma unroll
            for (int j = 0; j < 4; ++j) acc[mt][nt][j] = 0.0f;

    const int aoff = (wm << 10) + (lane << 2);    // wm*4 blocks *256 + lane*4
    const int boff = (wn << 9)  + (lane << 1);    // wn*4 blocks *128 + lane*2

#pragma unroll 1
    for (int kc = 0; kc < NITER; ++kc) {
        const int cur = kc & 1;
        const float* Ab = As[cur];
        const float* Bb = Bs[cur];
        cp_wait<1>();
        __syncthreads();

#pragma unroll
        for (int ks = 0; ks < 2; ++ks) {
            uint4 af[4];
            uint2 bf[4];
#pragma unroll
            for (int mt = 0; mt < 4; ++mt)
                af[mt] = *(const uint4*)&Ab[aoff + (mt << 8) + (ks << 7)];
#pragma unroll
            for (int nt = 0; nt < 4; ++nt)
                bf[nt] = *(const uint2*)&Bb[boff + (nt << 7) + (ks << 6)];
#pragma unroll
            for (int mt = 0; mt < 4; ++mt)
#pragma unroll
                for (int nt = 0; nt < 4; ++nt)
                    mma_tf32(acc[mt][nt], (const unsigned*)&af[mt],
                             (const unsigned*)&bf[nt]);
        }
        __syncthreads();

        const int kn = (kc + 2 < NITER) ? kc + 2 : 0;   // tail dummy
        load_stage(cur, kn);
        cp_commit();
    }

    // Epilogue: bias (+residual), optional tf32 rounding, float2 stores
#pragma unroll
    for (int nt = 0; nt < 4; ++nt) {
        const int c = col0 + wn * 32 + nt * 8 + 2 * t;
        const float2 bb = *(const float2*)&bias[c];
#pragma unroll
        for (int mt = 0; mt < 4; ++mt) {
            const int r = row0 + wm * 64 + mt * 16 + g;
            float2 o0 = make_float2(acc[mt][nt][0] + bb.x, acc[mt][nt][1] + bb.y);
            float2 o1 = make_float2(acc[mt][nt][2] + bb.x, acc[mt][nt][3] + bb.y);
            if (RES) {
                const float2 r0v = *(const float2*)&res_y[(size_t)r * ND + c];
                const float2 r1v = *(const float2*)&res_y[(size_t)(r + 8) * ND + c];
                o0.x += r0v.x; o0.y += r0v.y;
                o1.x += r1v.x; o1.y += r1v.y;
            }
            if (ROUND) {
                o0.x = rtf(o0.x); o0.y = rtf(o0.y);
                o1.x = rtf(o1.x); o1.y = rtf(o1.y);
            }
            *(float2*)&C[(size_t)r * ND + c]       = o0;
            *(float2*)&C[(size_t)(r + 8) * ND + c] = o1;
        }
    }
}

__global__ __launch_bounds__(256, 2) void qkv_gemm(
    const float* __restrict__ bq, const float* __restrict__ bk,
    const float* __restrict__ bv)
{
    const float* W = g_wr + (size_t)blockIdx.z * ND * ND;
    const float* bias = (blockIdx.z == 0) ? bq : (blockIdx.z == 1) ? bk : bv;
    float* C = (blockIdx.z == 0) ? g_q : (blockIdx.z == 1) ? g_k : g_v;
    gemm_body<false, true>(g_yr, W, bias, nullptr, C);
}

__global__ __launch_bounds__(256, 2) void proj_gemm(
    const float* __restrict__ bm, const float* __restrict__ res_y)
{
    gemm_body<true, false>(g_o, g_wr + (size_t)3 * ND * ND, bm, res_y, g_x);
}

// ---------------------------------------------------------------------------
// Flash attention, tf32 mma (R9-proven body). Epilogue writes g_o in the
// A-permuted layout (proj_gemm's input). Static smem 36352B.
// ---------------------------------------------------------------------------
__global__ __launch_bounds__(256, 2) void attn_mma()
{
    __shared__ unsigned Ks[32 * 68];
    __shared__ unsigned Vs[32 * 72];
    __shared__ unsigned Ps[128 * 36];

    const int tid  = threadIdx.x;
    const int warp = tid >> 5, lane = tid & 31;
    const int g = lane >> 2, t = lane & 3;
    const int b  = blockIdx.y >> 4;
    const int h  = blockIdx.y & 15;
    const int q0 = blockIdx.x << 7;

    // Q fragments (pre-scaled by 1/8; exact on tf32 values)
    unsigned qf[8][4];
    {
        const int r0 = b * NS + q0 + warp * 16 + g;
        const float* qp  = g_q + ((size_t)r0 << 10) + (h << 6);
        const float* qp8 = qp + ((size_t)8 << 10);
#pragma unroll
        for (int ks = 0; ks < 8; ++ks) {
            const int c = ks * 8 + t;
            qf[ks][0] = __float_as_uint(qp[c] * 0.125f);
            qf[ks][1] = __float_as_uint(qp8[c] * 0.125f);
            qf[ks][2] = __float_as_uint(qp[c + 4] * 0.125f);
            qf[ks][3] = __float_as_uint(qp8[c + 4] * 0.125f);
        }
    }

    float of[8][4];
#pragma unroll
    for (int nt = 0; nt < 8; ++nt)
#pragma unroll
        for (int j = 0; j < 4; ++j) of[nt][j] = 0.0f;
    float m0 = -1e30f, m1 = -1e30f, l0 = 0.0f, l1 = 0.0f;

    const size_t kvbase = ((size_t)b << 20) + (size_t)(h << 6);
    const int key = tid >> 3;
    const int cb  = (tid & 7) << 3;

#pragma unroll 1
    for (int kc = 0; kc < 32; ++kc) {
        const int key0 = kc << 5;
        __syncthreads();
        {
            const float* kp = g_k + kvbase + ((size_t)(key0 + key) << 10) + cb;
            const float* vp = g_v + kvbase + ((size_t)(key0 + key) << 10) + cb;
            unsigned* kd = &Ks[key * 68 + cb];
            unsigned* vd = &Vs[key * 72 + cb];
            *(uint4*)kd       = *(const uint4*)kp;
            *(uint4*)(kd + 4) = *(const uint4*)(kp + 4);
            *(uint4*)vd       = *(const uint4*)vp;
            *(uint4*)(vd + 4) = *(const uint4*)(vp + 4);
        }
        __syncthreads();

        // S = Q @ K^T : warp band 16 x 32
        float sf[4][4];
#pragma unroll
        for (int nt = 0; nt < 4; ++nt)
#pragma unroll
            for (int j = 0; j < 4; ++j) sf[nt][j] = 0.0f;
#pragma unroll
        for (int ks = 0; ks < 8; ++ks) {
#pragma unroll
            for (int nt = 0; nt < 4; ++nt) {
                unsigned bf[2];
                const unsigned* p = &Ks[(nt * 8 + g) * 68 + ks * 8 + t];
                bf[0] = p[0];
                bf[1] = p[4];
                mma_tf32(sf[nt], qf[ks], bf);
            }
        }

        // mask bias
#pragma unroll
        for (int nt = 0; nt < 4; ++nt) {
            const float2 bb = *(const float2*)&g_bias[(b << 10) + key0 + nt * 8 + 2 * t];
            sf[nt][0] += bb.x; sf[nt][1] += bb.y;
            sf[nt][2] += bb.x; sf[nt][3] += bb.y;
        }

        // online softmax stats (lanes 4g+t: xor 1,2 stay in-row)
        float mx0 = -1e30f, mx1 = -1e30f;
#pragma unroll
        for (int nt = 0; nt < 4; ++nt) {
            mx0 = fmaxf(mx0, fmaxf(sf[nt][0], sf[nt][1]));
            mx1 = fmaxf(mx1, fmaxf(sf[nt][2], sf[nt][3]));
        }
        mx0 = fmaxf(mx0, __shfl_xor_sync(0xffffffffu, mx0, 1));
        mx0 = fmaxf(mx0, __shfl_xor_sync(0xffffffffu, mx0, 2));
        mx1 = fmaxf(mx1, __shfl_xor_sync(0xffffffffu, mx1, 1));
        mx1 = fmaxf(mx1, __shfl_xor_sync(0xffffffffu, mx1, 2));

        const float nm0 = fmaxf(m0, mx0);
        const float nm1 = fmaxf(m1, mx1);
        const float al0 = __expf(m0 - nm0);
        const float al1 = __expf(m1 - nm1);

        float sum0 = 0.0f, sum1 = 0.0f;
#pragma unroll
        for (int nt = 0; nt < 4; ++nt) {
            sf[nt][0] = __expf(sf[nt][0] - nm0);
            sf[nt][1] = __expf(sf[nt][1] - nm0);
            sf[nt][2] = __expf(sf[nt][2] - nm1);
            sf[nt][3] = __expf(sf[nt][3] - nm1);
            sum0 += sf[nt][0] + sf[nt][1];
            sum1 += sf[nt][2] + sf[nt][3];
        }
        sum0 += __shfl_xor_sync(0xffffffffu, sum0, 1);
        sum0 += __shfl_xor_sync(0xffffffffu, sum0, 2);
        sum1 += __shfl_xor_sync(0xffffffffu, sum1, 1);
        sum1 += __shfl_xor_sync(0xffffffffu, sum1, 2);
        l0 = l0 * al0 + sum0;  m0 = nm0;
        l1 = l1 * al1 + sum1;  m1 = nm1;

        // P fragments (tf32-rounded) -> own-warp smem rows
        {
            const int pr = warp * 16 + g;
#pragma unroll
            for (int nt = 0; nt < 4; ++nt) {
                const int c = nt * 8 + 2 * t;
                Ps[pr * 36 + c]           = f2tf(sf[nt][0]);
                Ps[pr * 36 + c + 1]       = f2tf(sf[nt][1]);
                Ps[(pr + 8) * 36 + c]     = f2tf(sf[nt][2]);
                Ps[(pr + 8) * 36 + c + 1] = f2tf(sf[nt][3]);
            }
        }
        __syncwarp();

        // O = O*alpha + P @ V
#pragma unroll
        for (int nt = 0; nt < 8; ++nt) {
            of[nt][0] *= al0; of[nt][1] *= al0;
            of[nt][2] *= al1; of[nt][3] *= al1;
        }
#pragma unroll
        for (int kt = 0; kt < 4; ++kt) {
            unsigned af[4];
            const unsigned* p = &Ps[(warp * 16 + g) * 36 + kt * 8 + t];
            af[0] = p[0];
            af[1] = p[8 * 36];
            af[2] = p[4];
            af[3] = p[8 * 36 + 4];
#pragma unroll
            for (int nt = 0; nt < 8; ++nt) {
                unsigned bf[2];
                bf[0] = Vs[(kt * 8 + t) * 72 + nt * 8 + g];
                bf[1] = Vs[(kt * 8 + t + 4) * 72 + nt * 8 + g];
                mma_tf32(of[nt], af, bf);
            }
        }
    }

    // finalize: divide by l, round to tf32, store into A-PERMUTED g_o
    const float r0i = 1.0f / l0;
    const float r1i = 1.0f / l1;
    const int grow = b * NS + q0 + warp * 16 + g;
#pragma unroll
    for (int nt = 0; nt < 8; ++nt) {
        const int c = (h << 6) + nt * 8 + 2 * t;
        g_o[permA(grow,     c    )] = rtf(of[nt][0] * r0i);
        g_o[permA(grow,     c + 1)] = rtf(of[nt][1] * r0i);
        g_o[permA(grow + 8, c    )] = rtf(of[nt][2] * r1i);
        g_o[permA(grow + 8, c + 1)] = rtf(of[nt][3] * r1i);
    }
}

// ---------------------------------------------------------------------------
// LayerNorm (torch semantics): unbiased std (ddof=1), eps added to std.
// ---------------------------------------------------------------------------
__global__ __launch_bounds__(256) void ln_kernel(
    const float* __restrict__ a2, const float* __restrict__ b2,
    float* __restrict__ out)
{
    const int row = blockIdx.x;
    const int tid = threadIdx.x;
    const float* xr = g_x + (size_t)row * ND;
    const float4 v = *(const float4*)(xr + 4 * tid);

    float s  = v.x + v.y + v.z + v.w;
    float sq = v.x * v.x + v.y * v.y + v.z * v.z + v.w * v.w;
#pragma unroll
    for (int o = 16; o > 0; o >>= 1) {
        s  += __shfl_xor_sync(0xffffffffu, s, o);
        sq += __shfl_xor_sync(0xffffffffu, sq, o);
    }
    __shared__ float sh_s[8], sh_q[8];
    const int w = tid >> 5, ln = tid & 31;
    if (ln == 0) { sh_s[w] = s; sh_q[w] = sq; }
    __syncthreads();
    if (w == 0) {
        s  = (ln < 8) ? sh_s[ln] : 0.0f;
        sq = (ln < 8) ? sh_q[ln] : 0.0f;
#pragma unroll
        for (int o = 4; o > 0; o >>= 1) {
            s  += __shfl_xor_sync(0xffffffffu, s, o);
            sq += __shfl_xor_sync(0xffffffffu, sq, o);
        }
        if (ln == 0) { sh_s[0] = s; sh_q[0] = sq; }
    }
    __syncthreads();
    s  = sh_s[0];
    sq = sh_q[0];

    const float mean = s * (1.0f / 1024.0f);
    const float var  = (sq - s * mean) * (1.0f / 1023.0f);
    const float inv  = 1.0f / (sqrtf(fmaxf(var, 0.0f)) + 1e-6f);

    const float4 av = *(const float4*)(a2 + 4 * tid);
    const float4 bv = *(const float4*)(b2 + 4 * tid);
    float4 o;
    o.x = av.x * (v.x - mean) * inv + bv.x;
    o.y = av.y * (v.y - mean) * inv + bv.y;
    o.z = av.z * (v.z - mean) * inv + bv.z;
    o.w = av.w * (v.w - mean) * inv + bv.w;
    *(float4*)(out + (size_t)row * ND + 4 * tid) = o;
}

// ---------------------------------------------------------------------------
// Launch (no attribute calls, no dynamic smem — all static <= 48KB)
// ---------------------------------------------------------------------------
extern "C" void kernel_launch(void* const* d_in, const int* in_sizes, int n_in,
                              void* d_out, int out_size)
{
    const float* y  = (const float*)d_in[0];
    const void*  mk = d_in[1];
    const float* Wq = (const float*)d_in[2];
    const float* bq = (const float*)d_in[3];
    const float* Wk = (const float*)d_in[4];
    const float* bk = (const float*)d_in[5];
    const float* Wv = (const float*)d_in[6];
    const float* bv = (const float*)d_in[7];
    const float* Wm = (const float*)d_in[8];
    const float* bm = (const float*)d_in[9];
    const float* a2 = (const float*)d_in[10];
    const float* b2 = (const float*)d_in[11];
    float* out = (float*)d_out;

    mask_convert<<<1, 256>>>(mk);
    round_tf32<<<(MROWS * ND / 4 + 4 * ND * ND / 4) / 256, 256>>>(y, Wq, Wk, Wv, Wm);

    qkv_gemm<<<dim3(ND / 128, MROWS / 128, 3), 256>>>(bq, bk, bv);

    attn_mma<<<dim3(NS / 128, NB * NH), 256>>>();   // (8, 128)

    proj_gemm<<<dim3(ND / 128, MROWS / 128), 256>>>(bm, y);

    ln_kernel<<<MROWS, 256>>>(a2, b2, out);
}